// round 4
// baseline (speedup 1.0000x reference)
#include <cuda_runtime.h>
#include <cuda_bf16.h>
#include <cstdint>

#define TOKENS 16384
#define HDIM   1024
#define FDIM   4096
#define WSZ    (FDIM*HDIM)

// ---------------- scratch (static device, no allocations) ----------------
__device__ int8_t g_xq  [(size_t)TOKENS*HDIM];   // 16 MB quantized rmsnorm(x)
__device__ int8_t g_wupq[WSZ];                   //  4 MB ternary w_up
__device__ int8_t g_wdnq[WSZ];                   //  4 MB ternary w_down
__device__ int8_t g_h2q [(size_t)TOKENS*FDIM];   // 64 MB quantized relu^2
__device__ int    g_up  [(size_t)TOKENS*FDIM];   // 256 MB GEMM1 result (exact ints)
__device__ float  g_mul1[TOKENS];
__device__ int    g_rowmax[TOKENS];              // relu-max of up (s32, >=0)
__device__ float  g_part[2048];
__device__ float  g_mw[2];                       // clip(mean|w_up|), clip(mean|w_dn|)

// ---------------- helpers ----------------
__device__ __forceinline__ uint32_t smem_u32(const void* p) {
    uint32_t a;
    asm("{ .reg .u64 t; cvta.to.shared.u64 t, %1; cvt.u32.u64 %0, t; }" : "=r"(a) : "l"(p));
    return a;
}
__device__ __forceinline__ void cp_async16(uint32_t smem, const void* gmem) {
    asm volatile("cp.async.cg.shared.global [%0], [%1], 16;" :: "r"(smem), "l"(gmem));
}
__device__ __forceinline__ void mma_s8(int* c, const uint32_t* a, const uint32_t* b) {
    asm volatile(
        "mma.sync.aligned.m16n8k32.row.col.s32.s8.s8.s32 "
        "{%0,%1,%2,%3}, {%4,%5,%6,%7}, {%8,%9}, {%0,%1,%2,%3};"
        : "+r"(c[0]), "+r"(c[1]), "+r"(c[2]), "+r"(c[3])
        : "r"(a[0]), "r"(a[1]), "r"(a[2]), "r"(a[3]), "r"(b[0]), "r"(b[1]));
}
__device__ __forceinline__ void ldm_x4(uint32_t* r, uint32_t addr) {
    asm volatile("ldmatrix.sync.aligned.m8n8.x4.shared.b16 {%0,%1,%2,%3}, [%4];"
        : "=r"(r[0]), "=r"(r[1]), "=r"(r[2]), "=r"(r[3]) : "r"(addr));
}

// ---------------- elementwise kernels ----------------

__global__ void k_reduce_abs(const float* __restrict__ wup, const float* __restrict__ wdn) {
    __shared__ float sh[256];
    int b = blockIdx.x;
    const float4* p = (const float4*)((b < 1024) ? wup : wdn);
    int bb = b & 1023;
    float s = 0.f;
    int base = bb * 1024 + threadIdx.x;
#pragma unroll
    for (int i = 0; i < 4; i++) {
        float4 v = p[base + i * 256];
        s += fabsf(v.x) + fabsf(v.y) + fabsf(v.z) + fabsf(v.w);
    }
    sh[threadIdx.x] = s; __syncthreads();
    for (int o = 128; o > 0; o >>= 1) {
        if (threadIdx.x < o) sh[threadIdx.x] += sh[threadIdx.x + o];
        __syncthreads();
    }
    if (threadIdx.x == 0) g_part[b] = sh[0];
}

__global__ void k_finalize_mw() {
    __shared__ float sh[256];
    for (int half = 0; half < 2; half++) {
        float s = 0.f;
        for (int i = threadIdx.x; i < 1024; i += 256) s += g_part[half * 1024 + i];
        sh[threadIdx.x] = s; __syncthreads();
        for (int o = 128; o > 0; o >>= 1) {
            if (threadIdx.x < o) sh[threadIdx.x] += sh[threadIdx.x + o];
            __syncthreads();
        }
        if (threadIdx.x == 0) g_mw[half] = fmaxf(sh[0] / (float)WSZ, 1e-5f);
        __syncthreads();
    }
}

__global__ void k_ternarize(const float* __restrict__ w, int which) {
    int8_t* out = which ? g_wdnq : g_wupq;
    float s = 1.0f / g_mw[which];
    size_t i = (size_t)blockIdx.x * blockDim.x + threadIdx.x;   // float4 index
    float4 v = ((const float4*)w)[i];
    int q0 = (int)rintf(fminf(fmaxf(v.x * s, -1.f), 1.f));
    int q1 = (int)rintf(fminf(fmaxf(v.y * s, -1.f), 1.f));
    int q2 = (int)rintf(fminf(fmaxf(v.z * s, -1.f), 1.f));
    int q3 = (int)rintf(fminf(fmaxf(v.w * s, -1.f), 1.f));
    uint32_t pk = (uint32_t)(q0 & 0xFF) | ((uint32_t)(q1 & 0xFF) << 8) |
                  ((uint32_t)(q2 & 0xFF) << 16) | ((uint32_t)(q3 & 0xFF) << 24);
    ((uint32_t*)out)[i] = pk;
}

__global__ void k_rmsnorm_quant(const float* __restrict__ x, const float* __restrict__ nw) {
    __shared__ float sh[256];
    __shared__ float s_inv, s_scale;
    int t = blockIdx.x, tid = threadIdx.x;
    float4 v = ((const float4*)(x + (size_t)t * HDIM))[tid];
    float4 w = ((const float4*)nw)[tid];
    float ss = v.x * v.x + v.y * v.y + v.z * v.z + v.w * v.w;
    sh[tid] = ss; __syncthreads();
    for (int o = 128; o > 0; o >>= 1) { if (tid < o) sh[tid] += sh[tid + o]; __syncthreads(); }
    if (tid == 0) s_inv = 1.0f / sqrtf(sh[0] * (1.0f / HDIM) + 1e-6f);
    __syncthreads();
    float inv = s_inv;
    float h0 = v.x * inv * w.x, h1 = v.y * inv * w.y, h2 = v.z * inv * w.z, h3 = v.w * inv * w.w;
    float m = fmaxf(fmaxf(fabsf(h0), fabsf(h1)), fmaxf(fabsf(h2), fabsf(h3)));
    sh[tid] = m; __syncthreads();
    for (int o = 128; o > 0; o >>= 1) { if (tid < o) sh[tid] = fmaxf(sh[tid], sh[tid + o]); __syncthreads(); }
    if (tid == 0) {
        float cm = fmaxf(sh[0], 1e-5f);
        s_scale = 127.0f / cm;
        g_mul1[t] = (cm / 127.0f) * g_mw[0];
        g_rowmax[t] = 0;
    }
    __syncthreads();
    float sc = s_scale;
    int q0 = (int)rintf(fminf(fmaxf(h0 * sc, -128.f), 127.f));
    int q1 = (int)rintf(fminf(fmaxf(h1 * sc, -128.f), 127.f));
    int q2 = (int)rintf(fminf(fmaxf(h2 * sc, -128.f), 127.f));
    int q3 = (int)rintf(fminf(fmaxf(h3 * sc, -128.f), 127.f));
    uint32_t pk = (uint32_t)(q0 & 0xFF) | ((uint32_t)(q1 & 0xFF) << 8) |
                  ((uint32_t)(q2 & 0xFF) << 16) | ((uint32_t)(q3 & 0xFF) << 24);
    ((uint32_t*)(g_xq + (size_t)t * HDIM))[tid] = pk;
}

__global__ void k_relu2_quant() {
    size_t i = (size_t)blockIdx.x * 256 + threadIdx.x;    // int4 index over TOKENS*FDIM/4
    int t = (int)(i >> 10);
    float mul1 = g_mul1[t];
    float rm = (float)g_rowmax[t] * mul1;
    float sc2 = 127.0f / fmaxf(rm * rm, 1e-5f);
    int4 u = ((const int4*)g_up)[i];
    float a0 = fmaxf((float)u.x, 0.f) * mul1, a1 = fmaxf((float)u.y, 0.f) * mul1;
    float a2 = fmaxf((float)u.z, 0.f) * mul1, a3 = fmaxf((float)u.w, 0.f) * mul1;
    int q0 = (int)rintf(fminf(a0 * a0 * sc2, 127.f));
    int q1 = (int)rintf(fminf(a1 * a1 * sc2, 127.f));
    int q2 = (int)rintf(fminf(a2 * a2 * sc2, 127.f));
    int q3 = (int)rintf(fminf(a3 * a3 * sc2, 127.f));
    uint32_t pk = (uint32_t)(q0 & 0xFF) | ((uint32_t)(q1 & 0xFF) << 8) |
                  ((uint32_t)(q2 & 0xFF) << 16) | ((uint32_t)(q3 & 0xFF) << 24);
    ((uint32_t*)g_h2q)[i] = pk;
}

// ---------------- int8 mma.sync GEMM, ldmatrix + 4-stage cp.async ----------------
// C[m,n] = sum_k A[m0+m,k]*B[n0+n,k]; A,B int8 K-contiguous.
// Tile 128x128x64; 8 warps = 2(M) x 4(N); warp tile 64x32.
// SMEM rows padded to 80 B -> ldmatrix quadrants conflict-free.
// EPI==1: store s32 to g_up + fused per-row relu-max.
// EPI==2: out = C*mul2[m] + resid (float).

#define STAGES   4
#define TILE_B   10240            /* 128 rows * 80 B */
#define STAGE_B  (2*TILE_B)       /* A tile + B tile */
#define GEMM_SMEM (STAGES*STAGE_B)

template <int KTOT, int EPI>
__global__ void __launch_bounds__(256)
k_gemm(const float* __restrict__ resid, float* __restrict__ out2) {
    extern __shared__ __align__(16) int8_t smem[];
    __shared__ int s_rowmax[128];

    const int8_t* A = (EPI == 1) ? g_xq   : g_h2q;
    const int8_t* B = (EPI == 1) ? g_wupq : g_wdnq;
    const int KIT = KTOT / 64;

    int tid = threadIdx.x, wid = tid >> 5, lane = tid & 31;
    int wm = wid & 1, wn = wid >> 1;
    int m0 = blockIdx.y * 128, n0 = blockIdx.x * 128;
    int tg = lane & 3, gp = lane >> 2;
    uint32_t sbase = smem_u32(smem);

    if (EPI == 1 && tid < 128) s_rowmax[tid] = 0;

    // load decomposition: 512 granules of 16B per tile, 2 per thread
    int r0g = tid >> 2, c0g = tid & 3;
    int r1g = (tid + 256) >> 2, c1g = tid & 3;

    auto load_stage = [&](int stage, int kit) {
        int k0 = kit * 64;
        uint32_t dA = sbase + stage * STAGE_B;
        uint32_t dB = dA + TILE_B;
        cp_async16(dA + r0g * 80 + c0g * 16, A + (size_t)(m0 + r0g) * KTOT + k0 + c0g * 16);
        cp_async16(dA + r1g * 80 + c1g * 16, A + (size_t)(m0 + r1g) * KTOT + k0 + c1g * 16);
        cp_async16(dB + r0g * 80 + c0g * 16, B + (size_t)(n0 + r0g) * KTOT + k0 + c0g * 16);
        cp_async16(dB + r1g * 80 + c1g * 16, B + (size_t)(n0 + r1g) * KTOT + k0 + c1g * 16);
        asm volatile("cp.async.commit_group;" ::: "memory");
    };

    // ldmatrix per-lane offsets (within a stage)
    // A: quadrants (rows0-7,k0-15),(rows8-15,k0-15),(rows0-7,k16-31),(rows8-15,k16-31)
    uint32_t aOff = (uint32_t)((wm * 64 + (lane & 15)) * 80 + ((lane >> 4) << 4));
    // B: quadrants (n0-7,k0-15),(n0-7,k16-31),(n8-15,k0-15),(n8-15,k16-31)
    uint32_t bOff = (uint32_t)((wn * 32 + ((lane >> 4) << 3) + (lane & 7)) * 80 +
                               (((lane >> 3) & 1) << 4)) + TILE_B;

    int acc[4][4][4];
#pragma unroll
    for (int i = 0; i < 4; i++)
#pragma unroll
        for (int j = 0; j < 4; j++)
#pragma unroll
            for (int r = 0; r < 4; r++) acc[i][j][r] = 0;

#pragma unroll
    for (int s = 0; s < STAGES - 1; s++) load_stage(s, s);

    for (int it = 0; it < KIT; it++) {
        int cur = it & (STAGES - 1);
        asm volatile("cp.async.wait_group %0;" :: "n"(STAGES - 2) : "memory");
        __syncthreads();
        if (it + STAGES - 1 < KIT) load_stage((it + STAGES - 1) & (STAGES - 1), it + STAGES - 1);

        uint32_t sg = sbase + cur * STAGE_B;
#pragma unroll
        for (int ks = 0; ks < 2; ks++) {
            uint32_t kk = ks * 32;
            uint32_t a[4][4], b[2][4];
#pragma unroll
            for (int mt = 0; mt < 4; mt++)
                ldm_x4(a[mt], sg + aOff + mt * (16 * 80) + kk);
#pragma unroll
            for (int np = 0; np < 2; np++)
                ldm_x4(b[np], sg + bOff + np * (16 * 80) + kk);
#pragma unroll
            for (int mt = 0; mt < 4; mt++)
#pragma unroll
                for (int nt = 0; nt < 4; nt++)
                    mma_s8(acc[mt][nt], a[mt], b[nt >> 1] + (nt & 1) * 2);
        }
    }

    // ---------------- epilogue ----------------
    if (EPI == 1) {
#pragma unroll
        for (int mt = 0; mt < 4; mt++) {
            int lr0 = wm * 64 + mt * 16 + gp;
            int mx0 = 0, mx1 = 0;
#pragma unroll
            for (int nt = 0; nt < 4; nt++) {
                int col = n0 + wn * 32 + nt * 8 + tg * 2;
                int* d0 = g_up + (size_t)(m0 + lr0) * FDIM + col;
                int* d1 = g_up + (size_t)(m0 + lr0 + 8) * FDIM + col;
                *(int2*)d0 = make_int2(acc[mt][nt][0], acc[mt][nt][1]);
                *(int2*)d1 = make_int2(acc[mt][nt][2], acc[mt][nt][3]);
                mx0 = max(mx0, max(acc[mt][nt][0], acc[mt][nt][1]));
                mx1 = max(mx1, max(acc[mt][nt][2], acc[mt][nt][3]));
            }
            mx0 = max(mx0, __shfl_xor_sync(0xFFFFFFFFu, mx0, 1));
            mx0 = max(mx0, __shfl_xor_sync(0xFFFFFFFFu, mx0, 2));
            mx1 = max(mx1, __shfl_xor_sync(0xFFFFFFFFu, mx1, 1));
            mx1 = max(mx1, __shfl_xor_sync(0xFFFFFFFFu, mx1, 2));
            if (tg == 0) {
                atomicMax(&s_rowmax[lr0], mx0);
                atomicMax(&s_rowmax[lr0 + 8], mx1);
            }
        }
        __syncthreads();
        if (tid < 128) atomicMax(&g_rowmax[m0 + tid], s_rowmax[tid]);
    } else {
#pragma unroll
        for (int mt = 0; mt < 4; mt++) {
            int r0 = m0 + wm * 64 + mt * 16 + gp;
            int r1 = r0 + 8;
            float m1a = g_mul1[r0], m1b = g_mul1[r1];
            float rma = (float)g_rowmax[r0] * m1a, rmb = (float)g_rowmax[r1] * m1b;
            float mul2a = (fmaxf(rma * rma, 1e-5f) / 127.0f) * g_mw[1];
            float mul2b = (fmaxf(rmb * rmb, 1e-5f) / 127.0f) * g_mw[1];
#pragma unroll
            for (int nt = 0; nt < 4; nt++) {
                int col = n0 + wn * 32 + nt * 8 + tg * 2;
                const float2 ra = *(const float2*)(resid + (size_t)r0 * HDIM + col);
                const float2 rb = *(const float2*)(resid + (size_t)r1 * HDIM + col);
                float2 oa, ob;
                oa.x = (float)acc[mt][nt][0] * mul2a + ra.x;
                oa.y = (float)acc[mt][nt][1] * mul2a + ra.y;
                ob.x = (float)acc[mt][nt][2] * mul2b + rb.x;
                ob.y = (float)acc[mt][nt][3] * mul2b + rb.y;
                *(float2*)(out2 + (size_t)r0 * HDIM + col) = oa;
                *(float2*)(out2 + (size_t)r1 * HDIM + col) = ob;
            }
        }
    }
}

// ---------------- launch ----------------
extern "C" void kernel_launch(void* const* d_in, const int* in_sizes, int n_in,
                              void* d_out, int out_size) {
    const float* x   = (const float*)d_in[0];
    const float* nw  = (const float*)d_in[1];
    const float* wup = (const float*)d_in[2];
    const float* wdn = (const float*)d_in[3];
    float* out = (float*)d_out;

    cudaFuncSetAttribute(k_gemm<1024, 1>, cudaFuncAttributeMaxDynamicSharedMemorySize, GEMM_SMEM);
    cudaFuncSetAttribute(k_gemm<4096, 2>, cudaFuncAttributeMaxDynamicSharedMemorySize, GEMM_SMEM);

    k_reduce_abs<<<2048, 256>>>(wup, wdn);
    k_finalize_mw<<<1, 256>>>();
    k_ternarize<<<WSZ / 4 / 256, 256>>>(wup, 0);
    k_ternarize<<<WSZ / 4 / 256, 256>>>(wdn, 1);
    k_rmsnorm_quant<<<TOKENS, 256>>>(x, nw);
    k_gemm<1024, 1><<<dim3(FDIM / 128, TOKENS / 128), 256, GEMM_SMEM>>>(nullptr, nullptr);
    k_relu2_quant<<<(int)((size_t)TOKENS * FDIM / 4 / 256), 256>>>();
    k_gemm<4096, 2><<<dim3(HDIM / 128, TOKENS / 128), 256, GEMM_SMEM>>>(x, out);
}

// round 5
// speedup vs baseline: 1.0413x; 1.0413x over previous
#include <cuda_runtime.h>
#include <cuda_bf16.h>
#include <cstdint>

#define TOKENS 16384
#define HDIM   1024
#define FDIM   4096
#define WSZ    (FDIM*HDIM)

// ---------------- scratch (static device, no allocations) ----------------
// Tiled layout for all GEMM operands: tile = 128 rows x 64 k int8 = 8192 B
// contiguous, tiles ordered [row_block][k_block]. Within a tile, row r holds
// its 4 16B-chunks XOR-swizzled: phys_chunk = c ^ ((r>>1)&3)  (conflict-free
// ldmatrix quadrants).
__device__ __align__(1024) int8_t g_xq  [(size_t)TOKENS*HDIM];   // 16 MB
__device__ __align__(1024) int8_t g_wupq[WSZ];                   //  4 MB
__device__ __align__(1024) int8_t g_wdnq[WSZ];                   //  4 MB
__device__ __align__(1024) int8_t g_h2q [(size_t)TOKENS*FDIM];   // 64 MB
__device__ int    g_up  [(size_t)TOKENS*FDIM];   // 256 MB GEMM1 result (linear [t][f])
__device__ float  g_mul1[TOKENS];
__device__ int    g_rowmax[TOKENS];
__device__ float  g_part[2048];
__device__ float  g_mw[2];

// tiled address of the 4-byte word at (row R, col k) in a matrix with KB k-blocks
__device__ __forceinline__ size_t tiled_word(int R, int k, int KB) {
    int r = R & 127, mb = R >> 7, kb = k >> 6;
    int w = (k & 63) >> 2;                    // word index in row 0..15
    int c4 = (w >> 2) ^ ((r >> 1) & 3);       // swizzled 16B chunk
    return ((size_t)(mb * KB + kb) << 13) + (size_t)(r * 64 + (c4 << 4) + ((w & 3) << 2));
}

// ---------------- PTX helpers ----------------
__device__ __forceinline__ uint32_t smem_u32(const void* p) {
    uint32_t a;
    asm("{ .reg .u64 t; cvta.to.shared.u64 t, %1; cvt.u32.u64 %0, t; }" : "=r"(a) : "l"(p));
    return a;
}
__device__ __forceinline__ void mma_s8(int* c, const uint32_t* a, const uint32_t* b) {
    asm volatile(
        "mma.sync.aligned.m16n8k32.row.col.s32.s8.s8.s32 "
        "{%0,%1,%2,%3}, {%4,%5,%6,%7}, {%8,%9}, {%0,%1,%2,%3};"
        : "+r"(c[0]), "+r"(c[1]), "+r"(c[2]), "+r"(c[3])
        : "r"(a[0]), "r"(a[1]), "r"(a[2]), "r"(a[3]), "r"(b[0]), "r"(b[1]));
}
__device__ __forceinline__ void ldm_x4(uint32_t* r, uint32_t addr) {
    asm volatile("ldmatrix.sync.aligned.m8n8.x4.shared.b16 {%0,%1,%2,%3}, [%4];"
        : "=r"(r[0]), "=r"(r[1]), "=r"(r[2]), "=r"(r[3]) : "r"(addr));
}
__device__ __forceinline__ void cp_bulk(uint32_t dst, const void* src, uint32_t bytes, uint32_t mbar) {
    asm volatile(
        "cp.async.bulk.shared::cta.global.mbarrier::complete_tx::bytes [%0], [%1], %2, [%3];"
        :: "r"(dst), "l"(src), "r"(bytes), "r"(mbar) : "memory");
}
#define MBARRIER_INIT(addr, cnt) \
    asm volatile("mbarrier.init.shared.b64 [%0], %1;" :: "r"((uint32_t)(addr)), "r"((uint32_t)(cnt)) : "memory")
#define MBARRIER_EXPECT_TX(addr, tx) \
    asm volatile("mbarrier.arrive.expect_tx.shared.b64 _, [%0], %1;" :: "r"((uint32_t)(addr)), "r"((uint32_t)(tx)) : "memory")
#define MBARRIER_ARRIVE(addr) \
    asm volatile("mbarrier.arrive.shared.b64 _, [%0];" :: "r"((uint32_t)(addr)) : "memory")
#define MBARRIER_WAIT_PARITY(addr, parity) do {                                   \
    uint32_t _mbar = (uint32_t)(addr);                                            \
    uint32_t _par  = (uint32_t)(parity);                                          \
    asm volatile(                                                                 \
        "{\n\t.reg .pred P1;\n\t"                                                 \
        "WAIT_LOOP_%=:\n\t"                                                       \
        "mbarrier.try_wait.parity.acquire.cta.shared::cta.b64 P1, [%0], %1, 0x989680;\n\t" \
        "@P1 bra.uni WAIT_DONE_%=;\n\t"                                           \
        "bra.uni WAIT_LOOP_%=;\n\t"                                               \
        "WAIT_DONE_%=:\n\t}"                                                      \
        :: "r"(_mbar), "r"(_par) : "memory");                                     \
} while (0)

// ---------------- elementwise kernels ----------------

__global__ void k_reduce_abs(const float* __restrict__ wup, const float* __restrict__ wdn) {
    __shared__ float sh[256];
    int b = blockIdx.x;
    const float4* p = (const float4*)((b < 1024) ? wup : wdn);
    int bb = b & 1023;
    float s = 0.f;
    int base = bb * 1024 + threadIdx.x;
#pragma unroll
    for (int i = 0; i < 4; i++) {
        float4 v = p[base + i * 256];
        s += fabsf(v.x) + fabsf(v.y) + fabsf(v.z) + fabsf(v.w);
    }
    sh[threadIdx.x] = s; __syncthreads();
    for (int o = 128; o > 0; o >>= 1) {
        if (threadIdx.x < o) sh[threadIdx.x] += sh[threadIdx.x + o];
        __syncthreads();
    }
    if (threadIdx.x == 0) g_part[b] = sh[0];
}

__global__ void k_finalize_mw() {
    __shared__ float sh[256];
    for (int half = 0; half < 2; half++) {
        float s = 0.f;
        for (int i = threadIdx.x; i < 1024; i += 256) s += g_part[half * 1024 + i];
        sh[threadIdx.x] = s; __syncthreads();
        for (int o = 128; o > 0; o >>= 1) {
            if (threadIdx.x < o) sh[threadIdx.x] += sh[threadIdx.x + o];
            __syncthreads();
        }
        if (threadIdx.x == 0) g_mw[half] = fmaxf(sh[0] / (float)WSZ, 1e-5f);
        __syncthreads();
    }
}

// writes tiled ternary weights.  which=0: w_up (4096 rows, K=1024, KB=16)
//                               which=1: w_dn (1024 rows, K=4096, KB=64)
__global__ void k_ternarize(const float* __restrict__ w, int which) {
    int8_t* out = which ? g_wdnq : g_wupq;
    int K  = which ? FDIM : HDIM;
    int KB = K >> 6;
    float s = 1.0f / g_mw[which];
    size_t i = (size_t)blockIdx.x * blockDim.x + threadIdx.x;   // float4 index
    float4 v = ((const float4*)w)[i];
    int q0 = (int)rintf(fminf(fmaxf(v.x * s, -1.f), 1.f));
    int q1 = (int)rintf(fminf(fmaxf(v.y * s, -1.f), 1.f));
    int q2 = (int)rintf(fminf(fmaxf(v.z * s, -1.f), 1.f));
    int q3 = (int)rintf(fminf(fmaxf(v.w * s, -1.f), 1.f));
    uint32_t pk = (uint32_t)(q0 & 0xFF) | ((uint32_t)(q1 & 0xFF) << 8) |
                  ((uint32_t)(q2 & 0xFF) << 16) | ((uint32_t)(q3 & 0xFF) << 24);
    int R = (int)((4 * i) / K), k = (int)((4 * i) % K);
    *(uint32_t*)(out + tiled_word(R, k, KB)) = pk;
}

__global__ void k_rmsnorm_quant(const float* __restrict__ x, const float* __restrict__ nw) {
    __shared__ float sh[256];
    __shared__ float s_inv, s_scale;
    int t = blockIdx.x, tid = threadIdx.x;
    float4 v = ((const float4*)(x + (size_t)t * HDIM))[tid];
    float4 w = ((const float4*)nw)[tid];
    float ss = v.x * v.x + v.y * v.y + v.z * v.z + v.w * v.w;
    sh[tid] = ss; __syncthreads();
    for (int o = 128; o > 0; o >>= 1) { if (tid < o) sh[tid] += sh[tid + o]; __syncthreads(); }
    if (tid == 0) s_inv = 1.0f / sqrtf(sh[0] * (1.0f / HDIM) + 1e-6f);
    __syncthreads();
    float inv = s_inv;
    float h0 = v.x * inv * w.x, h1 = v.y * inv * w.y, h2 = v.z * inv * w.z, h3 = v.w * inv * w.w;
    float m = fmaxf(fmaxf(fabsf(h0), fabsf(h1)), fmaxf(fabsf(h2), fabsf(h3)));
    sh[tid] = m; __syncthreads();
    for (int o = 128; o > 0; o >>= 1) { if (tid < o) sh[tid] = fmaxf(sh[tid], sh[tid + o]); __syncthreads(); }
    if (tid == 0) {
        float cm = fmaxf(sh[0], 1e-5f);
        s_scale = 127.0f / cm;
        g_mul1[t] = (cm / 127.0f) * g_mw[0];
        g_rowmax[t] = 0;
    }
    __syncthreads();
    float sc = s_scale;
    int q0 = (int)rintf(fminf(fmaxf(h0 * sc, -128.f), 127.f));
    int q1 = (int)rintf(fminf(fmaxf(h1 * sc, -128.f), 127.f));
    int q2 = (int)rintf(fminf(fmaxf(h2 * sc, -128.f), 127.f));
    int q3 = (int)rintf(fminf(fmaxf(h3 * sc, -128.f), 127.f));
    uint32_t pk = (uint32_t)(q0 & 0xFF) | ((uint32_t)(q1 & 0xFF) << 8) |
                  ((uint32_t)(q2 & 0xFF) << 16) | ((uint32_t)(q3 & 0xFF) << 24);
    *(uint32_t*)(g_xq + tiled_word(t, 4 * tid, HDIM >> 6)) = pk;
}

__global__ void k_relu2_quant() {
    size_t i = (size_t)blockIdx.x * 256 + threadIdx.x;    // int4 index over TOKENS*FDIM/4
    int t = (int)(i >> 10);
    float mul1 = g_mul1[t];
    float rm = (float)g_rowmax[t] * mul1;
    float sc2 = 127.0f / fmaxf(rm * rm, 1e-5f);
    int4 u = ((const int4*)g_up)[i];
    float a0 = fmaxf((float)u.x, 0.f) * mul1, a1 = fmaxf((float)u.y, 0.f) * mul1;
    float a2 = fmaxf((float)u.z, 0.f) * mul1, a3 = fmaxf((float)u.w, 0.f) * mul1;
    int q0 = (int)rintf(fminf(a0 * a0 * sc2, 127.f));
    int q1 = (int)rintf(fminf(a1 * a1 * sc2, 127.f));
    int q2 = (int)rintf(fminf(a2 * a2 * sc2, 127.f));
    int q3 = (int)rintf(fminf(a3 * a3 * sc2, 127.f));
    uint32_t pk = (uint32_t)(q0 & 0xFF) | ((uint32_t)(q1 & 0xFF) << 8) |
                  ((uint32_t)(q2 & 0xFF) << 16) | ((uint32_t)(q3 & 0xFF) << 24);
    int f = (int)((i & 1023) << 2);
    *(uint32_t*)(g_h2q + tiled_word(t, f, FDIM >> 6)) = pk;
}

// ---------------- int8 mma.sync GEMM, bulk-copy + mbarrier pipeline ----------------
// Tile 128x128x64; 8 warps = 2(M) x 4(N); warp tile 64x32; 4 stages.
// Each stage = A tile 8KB + B tile 8KB loaded with TWO cp.async.bulk ops.
// EPI==1: store s32 to g_up (linear) + fused per-row relu-max.
// EPI==2: out = C*mul2[m] + resid (float).

#define STAGES    4
#define STAGE_B   16384
#define GEMM_SMEM (STAGES*STAGE_B)

template <int KTOT, int EPI>
__global__ void __launch_bounds__(256, 2)
k_gemm(const float* __restrict__ resid, float* __restrict__ out2) {
    extern __shared__ __align__(128) int8_t smem[];
    __shared__ __align__(8) uint64_t s_bar[2 * STAGES];   // [0..3] full, [4..7] empty
    __shared__ int s_rowmax[128];

    const int8_t* A = (EPI == 1) ? g_xq   : g_h2q;
    const int8_t* B = (EPI == 1) ? g_wupq : g_wdnq;
    const int KIT = KTOT / 64;
    const int KB  = KTOT / 64;

    int tid = threadIdx.x, wid = tid >> 5, lane = tid & 31;
    int wm = wid & 1, wn = wid >> 1;
    int mb = blockIdx.y, nb = blockIdx.x;
    int m0 = mb * 128, n0 = nb * 128;
    int tg = lane & 3, gp = lane >> 2;
    uint32_t sbase = smem_u32(smem);
    uint32_t barb  = smem_u32(s_bar);

    if (EPI == 1 && tid < 128) s_rowmax[tid] = 0;
    if (tid == 0) {
#pragma unroll
        for (int s = 0; s < STAGES; s++) {
            MBARRIER_INIT(barb + s * 8, 1);                 // full: 1 producer arrive + tx
            MBARRIER_INIT(barb + (STAGES + s) * 8, 256);    // empty: all threads arrive
        }
        asm volatile("fence.proxy.async.shared::cta;" ::: "memory");
    }
    __syncthreads();

    // per-lane fragment row/chunk components (within tile, 64B rows, swizzled chunks)
    int rA_base = wm * 64 + (lane & 15);        // + mt*16
    int qA = lane >> 4;                          // chunk bit from lane
    int rB_base = wn * 32 + ((lane >> 4) << 3) + (lane & 7);  // + np*16
    int qB = (lane >> 3) & 1;

    int acc[4][4][4];
#pragma unroll
    for (int i = 0; i < 4; i++)
#pragma unroll
        for (int j = 0; j < 4; j++)
#pragma unroll
            for (int r = 0; r < 4; r++) acc[i][j][r] = 0;

    int pstage = 0, pphase = 1;     // producer cursor (first empty-wait passes)
    int cphase = 0;                 // consumer cursor over full barriers

    auto produce = [&](int kit) {
        uint32_t fb = barb + pstage * 8;
        MBARRIER_WAIT_PARITY(barb + (STAGES + pstage) * 8, pphase);
        MBARRIER_EXPECT_TX(fb, 16384u);
        uint32_t dst = sbase + (uint32_t)pstage * STAGE_B;
        cp_bulk(dst,         A + ((size_t)(mb * KB + kit) << 13), 8192u, fb);
        cp_bulk(dst + 8192u, B + ((size_t)(nb * KB + kit) << 13), 8192u, fb);
        if (++pstage == STAGES) { pstage = 0; pphase ^= 1; }
    };

    if (tid == 0) {
#pragma unroll
        for (int s = 0; s < STAGES - 1; s++) produce(s);
    }

    for (int it = 0; it < KIT; it++) {
        int cur = it & (STAGES - 1);
        if (tid == 0 && it + STAGES - 1 < KIT) produce(it + STAGES - 1);

        MBARRIER_WAIT_PARITY(barb + cur * 8, cphase);
        uint32_t sA = sbase + (uint32_t)cur * STAGE_B;
        uint32_t sB = sA + 8192u;

        uint32_t a[2][4][4], b[2][2][4];
#pragma unroll
        for (int ks = 0; ks < 2; ks++) {
#pragma unroll
            for (int mt = 0; mt < 4; mt++) {
                int row = rA_base + mt * 16;
                int c4 = (ks * 2 + qA) ^ ((row >> 1) & 3);
                ldm_x4(a[ks][mt], sA + row * 64 + (c4 << 4));
            }
#pragma unroll
            for (int np = 0; np < 2; np++) {
                int row = rB_base + np * 16;
                int c4 = (ks * 2 + qB) ^ ((row >> 1) & 3);
                ldm_x4(b[ks][np], sB + row * 64 + (c4 << 4));
            }
        }
        MBARRIER_ARRIVE(barb + (STAGES + cur) * 8);
        if (cur == STAGES - 1) cphase ^= 1;

#pragma unroll
        for (int ks = 0; ks < 2; ks++)
#pragma unroll
            for (int mt = 0; mt < 4; mt++)
#pragma unroll
                for (int nt = 0; nt < 4; nt++)
                    mma_s8(acc[mt][nt], a[ks][mt], b[ks][nt >> 1] + (nt & 1) * 2);
    }

    // ---------------- epilogue ----------------
    if (EPI == 1) {
#pragma unroll
        for (int mt = 0; mt < 4; mt++) {
            int lr0 = wm * 64 + mt * 16 + gp;
            int mx0 = 0, mx1 = 0;
#pragma unroll
            for (int nt = 0; nt < 4; nt++) {
                int col = n0 + wn * 32 + nt * 8 + tg * 2;
                int* d0 = g_up + (size_t)(m0 + lr0) * FDIM + col;
                int* d1 = g_up + (size_t)(m0 + lr0 + 8) * FDIM + col;
                *(int2*)d0 = make_int2(acc[mt][nt][0], acc[mt][nt][1]);
                *(int2*)d1 = make_int2(acc[mt][nt][2], acc[mt][nt][3]);
                mx0 = max(mx0, max(acc[mt][nt][0], acc[mt][nt][1]));
                mx1 = max(mx1, max(acc[mt][nt][2], acc[mt][nt][3]));
            }
            mx0 = max(mx0, __shfl_xor_sync(0xFFFFFFFFu, mx0, 1));
            mx0 = max(mx0, __shfl_xor_sync(0xFFFFFFFFu, mx0, 2));
            mx1 = max(mx1, __shfl_xor_sync(0xFFFFFFFFu, mx1, 1));
            mx1 = max(mx1, __shfl_xor_sync(0xFFFFFFFFu, mx1, 2));
            if (tg == 0) {
                atomicMax(&s_rowmax[lr0], mx0);
                atomicMax(&s_rowmax[lr0 + 8], mx1);
            }
        }
        __syncthreads();
        if (tid < 128) atomicMax(&g_rowmax[m0 + tid], s_rowmax[tid]);
    } else {
#pragma unroll
        for (int mt = 0; mt < 4; mt++) {
            int r0 = m0 + wm * 64 + mt * 16 + gp;
            int r1 = r0 + 8;
            float m1a = g_mul1[r0], m1b = g_mul1[r1];
            float rma = (float)g_rowmax[r0] * m1a, rmb = (float)g_rowmax[r1] * m1b;
            float mul2a = (fmaxf(rma * rma, 1e-5f) / 127.0f) * g_mw[1];
            float mul2b = (fmaxf(rmb * rmb, 1e-5f) / 127.0f) * g_mw[1];
#pragma unroll
            for (int nt = 0; nt < 4; nt++) {
                int col = n0 + wn * 32 + nt * 8 + tg * 2;
                const float2 ra = *(const float2*)(resid + (size_t)r0 * HDIM + col);
                const float2 rb = *(const float2*)(resid + (size_t)r1 * HDIM + col);
                float2 oa, ob;
                oa.x = (float)acc[mt][nt][0] * mul2a + ra.x;
                oa.y = (float)acc[mt][nt][1] * mul2a + ra.y;
                ob.x = (float)acc[mt][nt][2] * mul2b + rb.x;
                ob.y = (float)acc[mt][nt][3] * mul2b + rb.y;
                *(float2*)(out2 + (size_t)r0 * HDIM + col) = oa;
                *(float2*)(out2 + (size_t)r1 * HDIM + col) = ob;
            }
        }
    }
}

// ---------------- launch ----------------
extern "C" void kernel_launch(void* const* d_in, const int* in_sizes, int n_in,
                              void* d_out, int out_size) {
    const float* x   = (const float*)d_in[0];
    const float* nw  = (const float*)d_in[1];
    const float* wup = (const float*)d_in[2];
    const float* wdn = (const float*)d_in[3];
    float* out = (float*)d_out;

    cudaFuncSetAttribute(k_gemm<1024, 1>, cudaFuncAttributeMaxDynamicSharedMemorySize, GEMM_SMEM);
    cudaFuncSetAttribute(k_gemm<4096, 2>, cudaFuncAttributeMaxDynamicSharedMemorySize, GEMM_SMEM);

    k_reduce_abs<<<2048, 256>>>(wup, wdn);
    k_finalize_mw<<<1, 256>>>();
    k_ternarize<<<WSZ / 4 / 256, 256>>>(wup, 0);
    k_ternarize<<<WSZ / 4 / 256, 256>>>(wdn, 1);
    k_rmsnorm_quant<<<TOKENS, 256>>>(x, nw);
    k_gemm<1024, 1><<<dim3(FDIM / 128, TOKENS / 128), 256, GEMM_SMEM>>>(nullptr, nullptr);
    k_relu2_quant<<<(int)((size_t)TOKENS * FDIM / 4 / 256), 256>>>();
    k_gemm<4096, 2><<<dim3(HDIM / 128, TOKENS / 128), 256, GEMM_SMEM>>>(x, out);
}

// round 6
// speedup vs baseline: 2.4966x; 2.3976x over previous
#include <cuda_runtime.h>
#include <cuda_bf16.h>
#include <cstdint>

#define TOKENS 16384
#define HDIM   1024
#define FDIM   4096
#define WSZ    (FDIM*HDIM)

// ---------------- scratch (static device, no allocations) ----------------
// Tiled bf16 layout for all GEMM operands: tile = 128 rows x 64 k = 16384 B,
// tiles ordered [row_block][k_block]. Within a tile, row r (128 B) holds 8
// 16B chunks, physically at chunk c ^ (r & 7)  -> ldmatrix conflict-free.
__device__ __align__(1024) __nv_bfloat16 g_xq  [(size_t)TOKENS*HDIM];   // 32 MB
__device__ __align__(1024) __nv_bfloat16 g_wupq[WSZ];                   //  8 MB
__device__ __align__(1024) __nv_bfloat16 g_wdnq[WSZ];                   //  8 MB
__device__ __align__(1024) __nv_bfloat16 g_h2q [(size_t)TOKENS*FDIM];   // 128 MB
__device__ float  g_up  [(size_t)TOKENS*FDIM];   // 256 MB GEMM1 result (exact ints, linear)
__device__ float  g_mul1[TOKENS];
__device__ int    g_rowmax[TOKENS];              // float bits, >= 0
__device__ float  g_part[2048];
__device__ float  g_mw[2];

// byte address of bf16 element (row R, col k) in tiled layout (KB k-blocks)
__device__ __forceinline__ size_t tiled_off16(int R, int k, int KB) {
    int r = R & 127, mb = R >> 7, kb = k >> 6;
    int c  = (k & 63) >> 3;           // chunk 0..7
    int c4 = c ^ (r & 7);
    return ((size_t)(mb * KB + kb) << 14) + (size_t)(r * 128 + (c4 << 4) + ((k & 7) << 1));
}

// ---------------- PTX helpers ----------------
__device__ __forceinline__ uint32_t smem_u32(const void* p) {
    uint32_t a;
    asm("{ .reg .u64 t; cvta.to.shared.u64 t, %1; cvt.u32.u64 %0, t; }" : "=r"(a) : "l"(p));
    return a;
}
__device__ __forceinline__ void mma_bf16(float* c, const uint32_t* a, uint32_t b0, uint32_t b1) {
    asm volatile(
        "mma.sync.aligned.m16n8k16.row.col.f32.bf16.bf16.f32 "
        "{%0,%1,%2,%3}, {%4,%5,%6,%7}, {%8,%9}, {%0,%1,%2,%3};"
        : "+f"(c[0]), "+f"(c[1]), "+f"(c[2]), "+f"(c[3])
        : "r"(a[0]), "r"(a[1]), "r"(a[2]), "r"(a[3]), "r"(b0), "r"(b1));
}
__device__ __forceinline__ void ldm_x4(uint32_t* r, uint32_t addr) {
    asm volatile("ldmatrix.sync.aligned.m8n8.x4.shared.b16 {%0,%1,%2,%3}, [%4];"
        : "=r"(r[0]), "=r"(r[1]), "=r"(r[2]), "=r"(r[3]) : "r"(addr));
}
__device__ __forceinline__ void cp_bulk(uint32_t dst, const void* src, uint32_t bytes, uint32_t mbar) {
    asm volatile(
        "cp.async.bulk.shared::cta.global.mbarrier::complete_tx::bytes [%0], [%1], %2, [%3];"
        :: "r"(dst), "l"(src), "r"(bytes), "r"(mbar) : "memory");
}
#define MBARRIER_INIT(addr, cnt) \
    asm volatile("mbarrier.init.shared.b64 [%0], %1;" :: "r"((uint32_t)(addr)), "r"((uint32_t)(cnt)) : "memory")
#define MBARRIER_EXPECT_TX(addr, tx) \
    asm volatile("mbarrier.arrive.expect_tx.shared.b64 _, [%0], %1;" :: "r"((uint32_t)(addr)), "r"((uint32_t)(tx)) : "memory")
#define MBARRIER_ARRIVE(addr) \
    asm volatile("mbarrier.arrive.shared.b64 _, [%0];" :: "r"((uint32_t)(addr)) : "memory")
#define MBARRIER_WAIT_PARITY(addr, parity) do {                                   \
    uint32_t _mbar = (uint32_t)(addr);                                            \
    uint32_t _par  = (uint32_t)(parity);                                          \
    asm volatile(                                                                 \
        "{\n\t.reg .pred P1;\n\t"                                                 \
        "WAIT_LOOP_%=:\n\t"                                                       \
        "mbarrier.try_wait.parity.acquire.cta.shared::cta.b64 P1, [%0], %1, 0x989680;\n\t" \
        "@P1 bra.uni WAIT_DONE_%=;\n\t"                                           \
        "bra.uni WAIT_LOOP_%=;\n\t"                                               \
        "WAIT_DONE_%=:\n\t}"                                                      \
        :: "r"(_mbar), "r"(_par) : "memory");                                     \
} while (0)

// ---------------- elementwise kernels ----------------

__global__ void k_reduce_abs(const float* __restrict__ wup, const float* __restrict__ wdn) {
    __shared__ float sh[256];
    int b = blockIdx.x;
    const float4* p = (const float4*)((b < 1024) ? wup : wdn);
    int bb = b & 1023;
    float s = 0.f;
    int base = bb * 1024 + threadIdx.x;
#pragma unroll
    for (int i = 0; i < 4; i++) {
        float4 v = p[base + i * 256];
        s += fabsf(v.x) + fabsf(v.y) + fabsf(v.z) + fabsf(v.w);
    }
    sh[threadIdx.x] = s; __syncthreads();
    for (int o = 128; o > 0; o >>= 1) {
        if (threadIdx.x < o) sh[threadIdx.x] += sh[threadIdx.x + o];
        __syncthreads();
    }
    if (threadIdx.x == 0) g_part[b] = sh[0];
}

__global__ void k_finalize_mw() {
    __shared__ float sh[256];
    for (int half = 0; half < 2; half++) {
        float s = 0.f;
        for (int i = threadIdx.x; i < 1024; i += 256) s += g_part[half * 1024 + i];
        sh[threadIdx.x] = s; __syncthreads();
        for (int o = 128; o > 0; o >>= 1) {
            if (threadIdx.x < o) sh[threadIdx.x] += sh[threadIdx.x + o];
            __syncthreads();
        }
        if (threadIdx.x == 0) g_mw[half] = fmaxf(sh[0] / (float)WSZ, 1e-5f);
        __syncthreads();
    }
}

// which=0: w_up (4096 rows, K=1024, KB=16); which=1: w_dn (1024 rows, K=4096, KB=64)
__global__ void k_ternarize(const float* __restrict__ w, int which) {
    __nv_bfloat16* out = which ? g_wdnq : g_wupq;
    int K  = which ? FDIM : HDIM;
    int KB = K >> 6;
    float s = 1.0f / g_mw[which];
    size_t i = (size_t)blockIdx.x * blockDim.x + threadIdx.x;   // float4 index
    float4 v = ((const float4*)w)[i];
    float q0 = rintf(fminf(fmaxf(v.x * s, -1.f), 1.f));
    float q1 = rintf(fminf(fmaxf(v.y * s, -1.f), 1.f));
    float q2 = rintf(fminf(fmaxf(v.z * s, -1.f), 1.f));
    float q3 = rintf(fminf(fmaxf(v.w * s, -1.f), 1.f));
    int R = (int)((4 * i) / K), k = (int)((4 * i) % K);
    char* p = (char*)out + tiled_off16(R, k, KB);
    *(__nv_bfloat162*)p       = __floats2bfloat162_rn(q0, q1);
    *(__nv_bfloat162*)(p + 4) = __floats2bfloat162_rn(q2, q3);
}

__global__ void k_rmsnorm_quant(const float* __restrict__ x, const float* __restrict__ nw) {
    __shared__ float sh[256];
    __shared__ float s_inv, s_scale;
    int t = blockIdx.x, tid = threadIdx.x;
    float4 v = ((const float4*)(x + (size_t)t * HDIM))[tid];
    float4 w = ((const float4*)nw)[tid];
    float ss = v.x * v.x + v.y * v.y + v.z * v.z + v.w * v.w;
    sh[tid] = ss; __syncthreads();
    for (int o = 128; o > 0; o >>= 1) { if (tid < o) sh[tid] += sh[tid + o]; __syncthreads(); }
    if (tid == 0) s_inv = 1.0f / sqrtf(sh[0] * (1.0f / HDIM) + 1e-6f);
    __syncthreads();
    float inv = s_inv;
    float h0 = v.x * inv * w.x, h1 = v.y * inv * w.y, h2 = v.z * inv * w.z, h3 = v.w * inv * w.w;
    float m = fmaxf(fmaxf(fabsf(h0), fabsf(h1)), fmaxf(fabsf(h2), fabsf(h3)));
    sh[tid] = m; __syncthreads();
    for (int o = 128; o > 0; o >>= 1) { if (tid < o) sh[tid] = fmaxf(sh[tid], sh[tid + o]); __syncthreads(); }
    if (tid == 0) {
        float cm = fmaxf(sh[0], 1e-5f);
        s_scale = 127.0f / cm;
        g_mul1[t] = (cm / 127.0f) * g_mw[0];
        g_rowmax[t] = 0;
    }
    __syncthreads();
    float sc = s_scale;
    float q0 = rintf(fminf(fmaxf(h0 * sc, -128.f), 127.f));
    float q1 = rintf(fminf(fmaxf(h1 * sc, -128.f), 127.f));
    float q2 = rintf(fminf(fmaxf(h2 * sc, -128.f), 127.f));
    float q3 = rintf(fminf(fmaxf(h3 * sc, -128.f), 127.f));
    char* p = (char*)g_xq + tiled_off16(t, 4 * tid, HDIM >> 6);
    *(__nv_bfloat162*)p       = __floats2bfloat162_rn(q0, q1);
    *(__nv_bfloat162*)(p + 4) = __floats2bfloat162_rn(q2, q3);
}

__global__ void k_relu2_quant() {
    size_t i = (size_t)blockIdx.x * 256 + threadIdx.x;    // float4 index over TOKENS*FDIM/4
    int t = (int)(i >> 10);
    float mul1 = g_mul1[t];
    float rm = __int_as_float(g_rowmax[t]) * mul1;
    float sc2 = 127.0f / fmaxf(rm * rm, 1e-5f);
    float4 u = ((const float4*)g_up)[i];
    float a0 = fmaxf(u.x, 0.f) * mul1, a1 = fmaxf(u.y, 0.f) * mul1;
    float a2 = fmaxf(u.z, 0.f) * mul1, a3 = fmaxf(u.w, 0.f) * mul1;
    float q0 = rintf(fminf(a0 * a0 * sc2, 127.f));
    float q1 = rintf(fminf(a1 * a1 * sc2, 127.f));
    float q2 = rintf(fminf(a2 * a2 * sc2, 127.f));
    float q3 = rintf(fminf(a3 * a3 * sc2, 127.f));
    int f = (int)((i & 1023) << 2);
    char* p = (char*)g_h2q + tiled_off16(t, f, FDIM >> 6);
    *(__nv_bfloat162*)p       = __floats2bfloat162_rn(q0, q1);
    *(__nv_bfloat162*)(p + 4) = __floats2bfloat162_rn(q2, q3);
}

// ---------------- bf16 mma.sync GEMM, bulk-copy + mbarrier pipeline ----------------
// Tile 128x128x64; 8 warps = 2(M) x 4(N); warp tile 64x32; 3 stages.
// Stage = A tile 16KB + B tile 16KB via two cp.async.bulk.
// EPI==1: store f32 (exact int) to g_up + fused per-row relu-max.
// EPI==2: out = C*mul2[m] + resid (float).

#define STAGES    3
#define STAGE_B   32768
#define GEMM_SMEM (STAGES*STAGE_B)

template <int KTOT, int EPI>
__global__ void __launch_bounds__(256, 2)
k_gemm(const float* __restrict__ resid, float* __restrict__ out2) {
    extern __shared__ __align__(128) int8_t smem[];
    __shared__ __align__(8) uint64_t s_bar[2 * STAGES];
    __shared__ int s_rowmax[128];

    const __nv_bfloat16* A = (EPI == 1) ? g_xq   : g_h2q;
    const __nv_bfloat16* B = (EPI == 1) ? g_wupq : g_wdnq;
    const int KIT = KTOT / 64;
    const int KB  = KTOT / 64;

    int tid = threadIdx.x, wid = tid >> 5, lane = tid & 31;
    int wm = wid & 1, wn = wid >> 1;
    int mb = blockIdx.y, nb = blockIdx.x;
    int m0 = mb * 128, n0 = nb * 128;
    int tg = lane & 3, gp = lane >> 2;
    uint32_t sbase = smem_u32(smem);
    uint32_t barb  = smem_u32(s_bar);

    if (EPI == 1 && tid < 128) s_rowmax[tid] = 0;
    if (tid == 0) {
#pragma unroll
        for (int s = 0; s < STAGES; s++) {
            MBARRIER_INIT(barb + s * 8, 1);
            MBARRIER_INIT(barb + (STAGES + s) * 8, 256);
        }
        asm volatile("fence.proxy.async.shared::cta;" ::: "memory");
    }
    __syncthreads();

    // ldmatrix lane components
    int aRow = wm * 64 + (lane & 15);                              // + mt*16
    int aCsel = lane >> 4;                                         // chunk low bit
    int bRow = wn * 32 + ((lane >> 3) & 1) * 8 + (lane & 7);       // + np*16
    int bCsel = lane >> 4;

    float acc[4][4][4];
#pragma unroll
    for (int i = 0; i < 4; i++)
#pragma unroll
        for (int j = 0; j < 4; j++)
#pragma unroll
            for (int r = 0; r < 4; r++) acc[i][j][r] = 0.f;

    int pstage = 0, pphase = 1;
    int cphase = 0;

    auto produce = [&](int kit) {
        uint32_t fb = barb + pstage * 8;
        MBARRIER_WAIT_PARITY(barb + (STAGES + pstage) * 8, pphase);
        MBARRIER_EXPECT_TX(fb, 32768u);
        uint32_t dst = sbase + (uint32_t)pstage * STAGE_B;
        cp_bulk(dst,          (const char*)A + ((size_t)(mb * KB + kit) << 14), 16384u, fb);
        cp_bulk(dst + 16384u, (const char*)B + ((size_t)(nb * KB + kit) << 14), 16384u, fb);
        if (++pstage == STAGES) { pstage = 0; pphase ^= 1; }
    };

    if (tid == 0) {
        produce(0);
        produce(1);
    }

    int cur = 0;
    for (int it = 0; it < KIT; it++) {
        if (tid == 0 && it + STAGES - 1 < KIT) produce(it + STAGES - 1);

        MBARRIER_WAIT_PARITY(barb + cur * 8, cphase);
        uint32_t sA = sbase + (uint32_t)cur * STAGE_B;
        uint32_t sB = sA + 16384u;

#pragma unroll
        for (int ks = 0; ks < 4; ks++) {
            uint32_t a[4][4], b[2][4];
#pragma unroll
            for (int mt = 0; mt < 4; mt++) {
                int row = aRow + mt * 16;
                int c4 = (2 * ks + aCsel) ^ (row & 7);
                ldm_x4(a[mt], sA + row * 128 + (c4 << 4));
            }
#pragma unroll
            for (int np = 0; np < 2; np++) {
                int row = bRow + np * 16;
                int c4 = (2 * ks + bCsel) ^ (row & 7);
                ldm_x4(b[np], sB + row * 128 + (c4 << 4));
            }
#pragma unroll
            for (int mt = 0; mt < 4; mt++)
#pragma unroll
                for (int np = 0; np < 2; np++)
#pragma unroll
                    for (int h = 0; h < 2; h++)
                        mma_bf16(acc[mt][np * 2 + h], a[mt], b[np][h], b[np][h + 2]);
        }
        MBARRIER_ARRIVE(barb + (STAGES + cur) * 8);
        if (++cur == STAGES) { cur = 0; cphase ^= 1; }
    }

    // ---------------- epilogue ----------------
    if (EPI == 1) {
#pragma unroll
        for (int mt = 0; mt < 4; mt++) {
            int lr0 = wm * 64 + mt * 16 + gp;
            float mx0 = 0.f, mx1 = 0.f;
#pragma unroll
            for (int nt = 0; nt < 4; nt++) {
                int col = n0 + wn * 32 + nt * 8 + tg * 2;
                float* d0 = g_up + (size_t)(m0 + lr0) * FDIM + col;
                float* d1 = g_up + (size_t)(m0 + lr0 + 8) * FDIM + col;
                *(float2*)d0 = make_float2(acc[mt][nt][0], acc[mt][nt][1]);
                *(float2*)d1 = make_float2(acc[mt][nt][2], acc[mt][nt][3]);
                mx0 = fmaxf(mx0, fmaxf(acc[mt][nt][0], acc[mt][nt][1]));
                mx1 = fmaxf(mx1, fmaxf(acc[mt][nt][2], acc[mt][nt][3]));
            }
            mx0 = fmaxf(mx0, __shfl_xor_sync(0xFFFFFFFFu, mx0, 1));
            mx0 = fmaxf(mx0, __shfl_xor_sync(0xFFFFFFFFu, mx0, 2));
            mx1 = fmaxf(mx1, __shfl_xor_sync(0xFFFFFFFFu, mx1, 1));
            mx1 = fmaxf(mx1, __shfl_xor_sync(0xFFFFFFFFu, mx1, 2));
            if (tg == 0) {
                atomicMax(&s_rowmax[lr0], __float_as_int(mx0));
                atomicMax(&s_rowmax[lr0 + 8], __float_as_int(mx1));
            }
        }
        __syncthreads();
        if (tid < 128) atomicMax(&g_rowmax[m0 + tid], s_rowmax[tid]);
    } else {
#pragma unroll
        for (int mt = 0; mt < 4; mt++) {
            int r0 = m0 + wm * 64 + mt * 16 + gp;
            int r1 = r0 + 8;
            float m1a = g_mul1[r0], m1b = g_mul1[r1];
            float rma = __int_as_float(g_rowmax[r0]) * m1a;
            float rmb = __int_as_float(g_rowmax[r1]) * m1b;
            float mul2a = (fmaxf(rma * rma, 1e-5f) / 127.0f) * g_mw[1];
            float mul2b = (fmaxf(rmb * rmb, 1e-5f) / 127.0f) * g_mw[1];
#pragma unroll
            for (int nt = 0; nt < 4; nt++) {
                int col = n0 + wn * 32 + nt * 8 + tg * 2;
                const float2 ra = *(const float2*)(resid + (size_t)r0 * HDIM + col);
                const float2 rb = *(const float2*)(resid + (size_t)r1 * HDIM + col);
                float2 oa, ob;
                oa.x = acc[mt][nt][0] * mul2a + ra.x;
                oa.y = acc[mt][nt][1] * mul2a + ra.y;
                ob.x = acc[mt][nt][2] * mul2b + rb.x;
                ob.y = acc[mt][nt][3] * mul2b + rb.y;
                *(float2*)(out2 + (size_t)r0 * HDIM + col) = oa;
                *(float2*)(out2 + (size_t)r1 * HDIM + col) = ob;
            }
        }
    }
}

// ---------------- launch ----------------
extern "C" void kernel_launch(void* const* d_in, const int* in_sizes, int n_in,
                              void* d_out, int out_size) {
    const float* x   = (const float*)d_in[0];
    const float* nw  = (const float*)d_in[1];
    const float* wup = (const float*)d_in[2];
    const float* wdn = (const float*)d_in[3];
    float* out = (float*)d_out;

    cudaFuncSetAttribute(k_gemm<1024, 1>, cudaFuncAttributeMaxDynamicSharedMemorySize, GEMM_SMEM);
    cudaFuncSetAttribute(k_gemm<4096, 2>, cudaFuncAttributeMaxDynamicSharedMemorySize, GEMM_SMEM);

    k_reduce_abs<<<2048, 256>>>(wup, wdn);
    k_finalize_mw<<<1, 256>>>();
    k_ternarize<<<WSZ / 4 / 256, 256>>>(wup, 0);
    k_ternarize<<<WSZ / 4 / 256, 256>>>(wdn, 1);
    k_rmsnorm_quant<<<TOKENS, 256>>>(x, nw);
    k_gemm<1024, 1><<<dim3(FDIM / 128, TOKENS / 128), 256, GEMM_SMEM>>>(nullptr, nullptr);
    k_relu2_quant<<<(int)((size_t)TOKENS * FDIM / 4 / 256), 256>>>();
    k_gemm<4096, 2><<<dim3(HDIM / 128, TOKENS / 128), 256, GEMM_SMEM>>>(x, out);
}

// round 7
// speedup vs baseline: 2.5170x; 1.0081x over previous
#include <cuda_runtime.h>
#include <cuda_bf16.h>
#include <cstdint>

#define TOKENS 16384
#define HDIM   1024
#define FDIM   4096
#define WSZ    (FDIM*HDIM)

// ---------------- scratch (static device, no allocations) ----------------
// Tiled bf16 layout for all GEMM operands: tile = 128 rows x 64 k = 16384 B,
// tiles ordered [row_block][k_block]. Within a tile, row r (128 B) holds 8
// 16B chunks, physically at chunk c ^ (r & 7)  -> ldmatrix conflict-free.
__device__ __align__(1024) __nv_bfloat16 g_xq  [(size_t)TOKENS*HDIM];   // 32 MB
__device__ __align__(1024) __nv_bfloat16 g_wupq[WSZ];                   //  8 MB
__device__ __align__(1024) __nv_bfloat16 g_wdnq[WSZ];                   //  8 MB
__device__ __align__(1024) __nv_bfloat16 g_h2q [(size_t)TOKENS*FDIM];   // 128 MB
__device__ int16_t g_up [(size_t)TOKENS*FDIM];   // 128 MB GEMM1 result (exact ints, linear)
__device__ float  g_mul1[TOKENS];
__device__ int    g_rowmax[TOKENS];              // float bits, >= 0
__device__ float  g_part[2048];
__device__ float  g_mw[2];

// byte address of bf16 element (row R, col k) in tiled layout (KB k-blocks)
__device__ __forceinline__ size_t tiled_off16(int R, int k, int KB) {
    int r = R & 127, mb = R >> 7, kb = k >> 6;
    int c  = (k & 63) >> 3;           // chunk 0..7
    int c4 = c ^ (r & 7);
    return ((size_t)(mb * KB + kb) << 14) + (size_t)(r * 128 + (c4 << 4) + ((k & 7) << 1));
}

// ---------------- PTX helpers ----------------
__device__ __forceinline__ uint32_t smem_u32(const void* p) {
    uint32_t a;
    asm("{ .reg .u64 t; cvta.to.shared.u64 t, %1; cvt.u32.u64 %0, t; }" : "=r"(a) : "l"(p));
    return a;
}
__device__ __forceinline__ void mma_bf16(float* c, const uint32_t* a, uint32_t b0, uint32_t b1) {
    asm volatile(
        "mma.sync.aligned.m16n8k16.row.col.f32.bf16.bf16.f32 "
        "{%0,%1,%2,%3}, {%4,%5,%6,%7}, {%8,%9}, {%0,%1,%2,%3};"
        : "+f"(c[0]), "+f"(c[1]), "+f"(c[2]), "+f"(c[3])
        : "r"(a[0]), "r"(a[1]), "r"(a[2]), "r"(a[3]), "r"(b0), "r"(b1));
}
__device__ __forceinline__ void ldm_x4(uint32_t* r, uint32_t addr) {
    asm volatile("ldmatrix.sync.aligned.m8n8.x4.shared.b16 {%0,%1,%2,%3}, [%4];"
        : "=r"(r[0]), "=r"(r[1]), "=r"(r[2]), "=r"(r[3]) : "r"(addr));
}
__device__ __forceinline__ void cp_bulk(uint32_t dst, const void* src, uint32_t bytes, uint32_t mbar) {
    asm volatile(
        "cp.async.bulk.shared::cta.global.mbarrier::complete_tx::bytes [%0], [%1], %2, [%3];"
        :: "r"(dst), "l"(src), "r"(bytes), "r"(mbar) : "memory");
}
#define MBARRIER_INIT(addr, cnt) \
    asm volatile("mbarrier.init.shared.b64 [%0], %1;" :: "r"((uint32_t)(addr)), "r"((uint32_t)(cnt)) : "memory")
#define MBARRIER_EXPECT_TX(addr, tx) \
    asm volatile("mbarrier.arrive.expect_tx.shared.b64 _, [%0], %1;" :: "r"((uint32_t)(addr)), "r"((uint32_t)(tx)) : "memory")
#define MBARRIER_ARRIVE(addr) \
    asm volatile("mbarrier.arrive.shared.b64 _, [%0];" :: "r"((uint32_t)(addr)) : "memory")
#define MBARRIER_WAIT_PARITY(addr, parity) do {                                   \
    uint32_t _mbar = (uint32_t)(addr);                                            \
    uint32_t _par  = (uint32_t)(parity);                                          \
    asm volatile(                                                                 \
        "{\n\t.reg .pred P1;\n\t"                                                 \
        "WAIT_LOOP_%=:\n\t"                                                       \
        "mbarrier.try_wait.parity.acquire.cta.shared::cta.b64 P1, [%0], %1, 0x989680;\n\t" \
        "@P1 bra.uni WAIT_DONE_%=;\n\t"                                           \
        "bra.uni WAIT_LOOP_%=;\n\t"                                               \
        "WAIT_DONE_%=:\n\t}"                                                      \
        :: "r"(_mbar), "r"(_par) : "memory");                                     \
} while (0)

// ---------------- elementwise kernels ----------------

__global__ void k_reduce_abs(const float* __restrict__ wup, const float* __restrict__ wdn) {
    __shared__ float sh[256];
    int b = blockIdx.x;
    const float4* p = (const float4*)((b < 1024) ? wup : wdn);
    int bb = b & 1023;
    float s = 0.f;
    int base = bb * 1024 + threadIdx.x;
#pragma unroll
    for (int i = 0; i < 4; i++) {
        float4 v = p[base + i * 256];
        s += fabsf(v.x) + fabsf(v.y) + fabsf(v.z) + fabsf(v.w);
    }
    sh[threadIdx.x] = s; __syncthreads();
    for (int o = 128; o > 0; o >>= 1) {
        if (threadIdx.x < o) sh[threadIdx.x] += sh[threadIdx.x + o];
        __syncthreads();
    }
    if (threadIdx.x == 0) g_part[b] = sh[0];
}

__global__ void k_finalize_mw() {
    __shared__ float sh[256];
    for (int half = 0; half < 2; half++) {
        float s = 0.f;
        for (int i = threadIdx.x; i < 1024; i += 256) s += g_part[half * 1024 + i];
        sh[threadIdx.x] = s; __syncthreads();
        for (int o = 128; o > 0; o >>= 1) {
            if (threadIdx.x < o) sh[threadIdx.x] += sh[threadIdx.x + o];
            __syncthreads();
        }
        if (threadIdx.x == 0) g_mw[half] = fmaxf(sh[0] / (float)WSZ, 1e-5f);
        __syncthreads();
    }
}

// which=0: w_up (4096 rows, K=1024, KB=16); which=1: w_dn (1024 rows, K=4096, KB=64)
__global__ void k_ternarize(const float* __restrict__ w, int which) {
    __nv_bfloat16* out = which ? g_wdnq : g_wupq;
    int K  = which ? FDIM : HDIM;
    int KB = K >> 6;
    float s = 1.0f / g_mw[which];
    size_t i = (size_t)blockIdx.x * blockDim.x + threadIdx.x;   // float4 index
    float4 v = ((const float4*)w)[i];
    float q0 = rintf(fminf(fmaxf(v.x * s, -1.f), 1.f));
    float q1 = rintf(fminf(fmaxf(v.y * s, -1.f), 1.f));
    float q2 = rintf(fminf(fmaxf(v.z * s, -1.f), 1.f));
    float q3 = rintf(fminf(fmaxf(v.w * s, -1.f), 1.f));
    int R = (int)((4 * i) / K), k = (int)((4 * i) % K);
    char* p = (char*)out + tiled_off16(R, k, KB);
    *(__nv_bfloat162*)p       = __floats2bfloat162_rn(q0, q1);
    *(__nv_bfloat162*)(p + 4) = __floats2bfloat162_rn(q2, q3);
}

__global__ void k_rmsnorm_quant(const float* __restrict__ x, const float* __restrict__ nw) {
    __shared__ float sh[256];
    __shared__ float s_inv, s_scale;
    int t = blockIdx.x, tid = threadIdx.x;
    float4 v = ((const float4*)(x + (size_t)t * HDIM))[tid];
    float4 w = ((const float4*)nw)[tid];
    float ss = v.x * v.x + v.y * v.y + v.z * v.z + v.w * v.w;
    sh[tid] = ss; __syncthreads();
    for (int o = 128; o > 0; o >>= 1) { if (tid < o) sh[tid] += sh[tid + o]; __syncthreads(); }
    if (tid == 0) s_inv = 1.0f / sqrtf(sh[0] * (1.0f / HDIM) + 1e-6f);
    __syncthreads();
    float inv = s_inv;
    float h0 = v.x * inv * w.x, h1 = v.y * inv * w.y, h2 = v.z * inv * w.z, h3 = v.w * inv * w.w;
    float m = fmaxf(fmaxf(fabsf(h0), fabsf(h1)), fmaxf(fabsf(h2), fabsf(h3)));
    sh[tid] = m; __syncthreads();
    for (int o = 128; o > 0; o >>= 1) { if (tid < o) sh[tid] = fmaxf(sh[tid], sh[tid + o]); __syncthreads(); }
    if (tid == 0) {
        float cm = fmaxf(sh[0], 1e-5f);
        s_scale = 127.0f / cm;
        g_mul1[t] = (cm / 127.0f) * g_mw[0];
        g_rowmax[t] = 0;
    }
    __syncthreads();
    float sc = s_scale;
    float q0 = rintf(fminf(fmaxf(h0 * sc, -128.f), 127.f));
    float q1 = rintf(fminf(fmaxf(h1 * sc, -128.f), 127.f));
    float q2 = rintf(fminf(fmaxf(h2 * sc, -128.f), 127.f));
    float q3 = rintf(fminf(fmaxf(h3 * sc, -128.f), 127.f));
    char* p = (char*)g_xq + tiled_off16(t, 4 * tid, HDIM >> 6);
    *(__nv_bfloat162*)p       = __floats2bfloat162_rn(q0, q1);
    *(__nv_bfloat162*)(p + 4) = __floats2bfloat162_rn(q2, q3);
}

// relu^2 + per-token absmax int8 quant; reads int16 up, writes tiled bf16
__global__ void k_relu2_quant() {
    size_t i = (size_t)blockIdx.x * 256 + threadIdx.x;    // group-of-4 index over TOKENS*FDIM/4
    int t = (int)(i >> 10);
    float mul1 = g_mul1[t];
    float rm = __int_as_float(g_rowmax[t]) * mul1;
    float sc2 = 127.0f / fmaxf(rm * rm, 1e-5f);
    short4 u = ((const short4*)g_up)[i];
    float a0 = fmaxf((float)u.x, 0.f) * mul1, a1 = fmaxf((float)u.y, 0.f) * mul1;
    float a2 = fmaxf((float)u.z, 0.f) * mul1, a3 = fmaxf((float)u.w, 0.f) * mul1;
    float q0 = rintf(fminf(a0 * a0 * sc2, 127.f));
    float q1 = rintf(fminf(a1 * a1 * sc2, 127.f));
    float q2 = rintf(fminf(a2 * a2 * sc2, 127.f));
    float q3 = rintf(fminf(a3 * a3 * sc2, 127.f));
    int f = (int)((i & 1023) << 2);
    char* p = (char*)g_h2q + tiled_off16(t, f, FDIM >> 6);
    *(__nv_bfloat162*)p       = __floats2bfloat162_rn(q0, q1);
    *(__nv_bfloat162*)(p + 4) = __floats2bfloat162_rn(q2, q3);
}

// ---------------- bf16 mma.sync GEMM, bulk-copy + mbarrier pipeline ----------------
// Tile 128x128x64; 8 warps = 2(M) x 4(N); warp tile 64x32; 3 stages.
// EPI==1: store int16 (exact) to g_up + fused per-row relu-max.
// EPI==2: out = C*mul2[m] + resid (float).

#define STAGES    3
#define STAGE_B   32768
#define GEMM_SMEM (STAGES*STAGE_B)

template <int KTOT, int EPI>
__global__ void __launch_bounds__(256, 2)
k_gemm(const float* __restrict__ resid, float* __restrict__ out2) {
    extern __shared__ __align__(128) int8_t smem[];
    __shared__ __align__(8) uint64_t s_bar[2 * STAGES];
    __shared__ int s_rowmax[128];

    const __nv_bfloat16* A = (EPI == 1) ? g_xq   : g_h2q;
    const __nv_bfloat16* B = (EPI == 1) ? g_wupq : g_wdnq;
    const int KIT = KTOT / 64;
    const int KB  = KTOT / 64;

    int tid = threadIdx.x, wid = tid >> 5, lane = tid & 31;
    int wm = wid & 1, wn = wid >> 1;
    int mb = blockIdx.y, nb = blockIdx.x;
    int m0 = mb * 128, n0 = nb * 128;
    int tg = lane & 3, gp = lane >> 2;
    uint32_t sbase = smem_u32(smem);
    uint32_t barb  = smem_u32(s_bar);

    if (EPI == 1 && tid < 128) s_rowmax[tid] = 0;
    if (tid == 0) {
#pragma unroll
        for (int s = 0; s < STAGES; s++) {
            MBARRIER_INIT(barb + s * 8, 1);
            MBARRIER_INIT(barb + (STAGES + s) * 8, 256);
        }
        asm volatile("fence.proxy.async.shared::cta;" ::: "memory");
    }
    __syncthreads();

    int aRow = wm * 64 + (lane & 15);
    int aCsel = lane >> 4;
    int bRow = wn * 32 + ((lane >> 3) & 1) * 8 + (lane & 7);
    int bCsel = lane >> 4;

    float acc[4][4][4];
#pragma unroll
    for (int i = 0; i < 4; i++)
#pragma unroll
        for (int j = 0; j < 4; j++)
#pragma unroll
            for (int r = 0; r < 4; r++) acc[i][j][r] = 0.f;

    int pstage = 0, pphase = 1;
    int cphase = 0;

    auto produce = [&](int kit) {
        uint32_t fb = barb + pstage * 8;
        MBARRIER_WAIT_PARITY(barb + (STAGES + pstage) * 8, pphase);
        MBARRIER_EXPECT_TX(fb, 32768u);
        uint32_t dst = sbase + (uint32_t)pstage * STAGE_B;
        cp_bulk(dst,          (const char*)A + ((size_t)(mb * KB + kit) << 14), 16384u, fb);
        cp_bulk(dst + 16384u, (const char*)B + ((size_t)(nb * KB + kit) << 14), 16384u, fb);
        if (++pstage == STAGES) { pstage = 0; pphase ^= 1; }
    };

    if (tid == 0) {
        produce(0);
        produce(1);
    }

    int cur = 0;
    for (int it = 0; it < KIT; it++) {
        if (tid == 0 && it + STAGES - 1 < KIT) produce(it + STAGES - 1);

        MBARRIER_WAIT_PARITY(barb + cur * 8, cphase);
        uint32_t sA = sbase + (uint32_t)cur * STAGE_B;
        uint32_t sB = sA + 16384u;

#pragma unroll
        for (int ks = 0; ks < 4; ks++) {
            uint32_t a[4][4], b[2][4];
#pragma unroll
            for (int mt = 0; mt < 4; mt++) {
                int row = aRow + mt * 16;
                int c4 = (2 * ks + aCsel) ^ (row & 7);
                ldm_x4(a[mt], sA + row * 128 + (c4 << 4));
            }
#pragma unroll
            for (int np = 0; np < 2; np++) {
                int row = bRow + np * 16;
                int c4 = (2 * ks + bCsel) ^ (row & 7);
                ldm_x4(b[np], sB + row * 128 + (c4 << 4));
            }
#pragma unroll
            for (int mt = 0; mt < 4; mt++)
#pragma unroll
                for (int np = 0; np < 2; np++)
#pragma unroll
                    for (int h = 0; h < 2; h++)
                        mma_bf16(acc[mt][np * 2 + h], a[mt], b[np][h], b[np][h + 2]);
        }
        MBARRIER_ARRIVE(barb + (STAGES + cur) * 8);
        if (++cur == STAGES) { cur = 0; cphase ^= 1; }
    }

    // ---------------- epilogue ----------------
    if (EPI == 1) {
#pragma unroll
        for (int mt = 0; mt < 4; mt++) {
            int lr0 = wm * 64 + mt * 16 + gp;
            float mx0 = 0.f, mx1 = 0.f;
#pragma unroll
            for (int nt = 0; nt < 4; nt++) {
                int col = n0 + wn * 32 + nt * 8 + tg * 2;
                int16_t* d0 = g_up + (size_t)(m0 + lr0) * FDIM + col;
                int16_t* d1 = g_up + (size_t)(m0 + lr0 + 8) * FDIM + col;
                int v00 = __float2int_rn(acc[mt][nt][0]);
                int v01 = __float2int_rn(acc[mt][nt][1]);
                int v10 = __float2int_rn(acc[mt][nt][2]);
                int v11 = __float2int_rn(acc[mt][nt][3]);
                *(uint32_t*)d0 = (uint32_t)(v00 & 0xFFFF) | ((uint32_t)v01 << 16);
                *(uint32_t*)d1 = (uint32_t)(v10 & 0xFFFF) | ((uint32_t)v11 << 16);
                mx0 = fmaxf(mx0, fmaxf(acc[mt][nt][0], acc[mt][nt][1]));
                mx1 = fmaxf(mx1, fmaxf(acc[mt][nt][2], acc[mt][nt][3]));
            }
            mx0 = fmaxf(mx0, __shfl_xor_sync(0xFFFFFFFFu, mx0, 1));
            mx0 = fmaxf(mx0, __shfl_xor_sync(0xFFFFFFFFu, mx0, 2));
            mx1 = fmaxf(mx1, __shfl_xor_sync(0xFFFFFFFFu, mx1, 1));
            mx1 = fmaxf(mx1, __shfl_xor_sync(0xFFFFFFFFu, mx1, 2));
            if (tg == 0) {
                atomicMax(&s_rowmax[lr0], __float_as_int(mx0));
                atomicMax(&s_rowmax[lr0 + 8], __float_as_int(mx1));
            }
        }
        __syncthreads();
        if (tid < 128) atomicMax(&g_rowmax[m0 + tid], s_rowmax[tid]);
    } else {
#pragma unroll
        for (int mt = 0; mt < 4; mt++) {
            int r0 = m0 + wm * 64 + mt * 16 + gp;
            int r1 = r0 + 8;
            float m1a = g_mul1[r0], m1b = g_mul1[r1];
            float rma = __int_as_float(g_rowmax[r0]) * m1a;
            float rmb = __int_as_float(g_rowmax[r1]) * m1b;
            float mul2a = (fmaxf(rma * rma, 1e-5f) / 127.0f) * g_mw[1];
            float mul2b = (fmaxf(rmb * rmb, 1e-5f) / 127.0f) * g_mw[1];
#pragma unroll
            for (int nt = 0; nt < 4; nt++) {
                int col = n0 + wn * 32 + nt * 8 + tg * 2;
                const float2 ra = *(const float2*)(resid + (size_t)r0 * HDIM + col);
                const float2 rb = *(const float2*)(resid + (size_t)r1 * HDIM + col);
                float2 oa, ob;
                oa.x = acc[mt][nt][0] * mul2a + ra.x;
                oa.y = acc[mt][nt][1] * mul2a + ra.y;
                ob.x = acc[mt][nt][2] * mul2b + rb.x;
                ob.y = acc[mt][nt][3] * mul2b + rb.y;
                *(float2*)(out2 + (size_t)r0 * HDIM + col) = oa;
                *(float2*)(out2 + (size_t)r1 * HDIM + col) = ob;
            }
        }
    }
}

// ---------------- launch ----------------
extern "C" void kernel_launch(void* const* d_in, const int* in_sizes, int n_in,
                              void* d_out, int out_size) {
    const float* x   = (const float*)d_in[0];
    const float* nw  = (const float*)d_in[1];
    const float* wup = (const float*)d_in[2];
    const float* wdn = (const float*)d_in[3];
    float* out = (float*)d_out;

    cudaFuncSetAttribute(k_gemm<1024, 1>, cudaFuncAttributeMaxDynamicSharedMemorySize, GEMM_SMEM);
    cudaFuncSetAttribute(k_gemm<4096, 2>, cudaFuncAttributeMaxDynamicSharedMemorySize, GEMM_SMEM);

    k_reduce_abs<<<2048, 256>>>(wup, wdn);
    k_finalize_mw<<<1, 256>>>();
    k_ternarize<<<WSZ / 4 / 256, 256>>>(wup, 0);
    k_ternarize<<<WSZ / 4 / 256, 256>>>(wdn, 1);
    k_rmsnorm_quant<<<TOKENS, 256>>>(x, nw);
    k_gemm<1024, 1><<<dim3(FDIM / 128, TOKENS / 128), 256, GEMM_SMEM>>>(nullptr, nullptr);
    k_relu2_quant<<<(int)((size_t)TOKENS * FDIM / 4 / 256), 256>>>();
    k_gemm<4096, 2><<<dim3(HDIM / 128, TOKENS / 128), 256, GEMM_SMEM>>>(x, out);
}